// round 13
// baseline (speedup 1.0000x reference)
#include <cuda_runtime.h>
#include <math.h>

#define NG   4
#define NB   6
#define NF   8
#define NFRR 256
#define NACT 5
#define BTOT 32768

// Precomputed factorization of relation similarity:
// sim[g,n,m]*16 = feat_n^T M_g feat_m + vt_g.feat_n + vp_g.feat_m + c_g
__device__ float g_M[NG][NF * NF];
__device__ float g_vt[NG][NF];
__device__ float g_vp[NG][NF];
__device__ float g_c[NG];

__global__ void precompute_kernel(const float* __restrict__ Wt,
                                  const float* __restrict__ bt,
                                  const float* __restrict__ Wp,
                                  const float* __restrict__ bp)
{
    int g   = blockIdx.x;
    int tid = threadIdx.x;                 // 256 threads
    const float* wt  = Wt + g * NFRR * NF;
    const float* wp  = Wp + g * NFRR * NF;
    const float* btg = bt + g * NFRR;
    const float* bpg = bp + g * NFRR;
    __shared__ float red[256];

    int ef = tid & 63, q = tid >> 6;
    int e  = ef >> 3,  f = ef & 7;
    float acc = 0.f;
#pragma unroll 8
    for (int r = q * 64; r < q * 64 + 64; r++)
        acc = fmaf(wt[r * NF + e], wp[r * NF + f], acc);
    red[tid] = acc;
    __syncthreads();
    if (q == 0)
        g_M[g][ef] = (red[ef] + red[64 + ef]) + (red[128 + ef] + red[192 + ef]);
    __syncthreads();

    float a2 = 0.f;
    if (tid < 64) {
        int ff = tid & 7, s = tid >> 3;
#pragma unroll 8
        for (int r = s * 32; r < s * 32 + 32; r++)
            a2 = fmaf(wt[r * NF + ff], bpg[r], a2);
        red[tid] = a2;
    } else if (tid < 128) {
        int id = tid - 64, ff = id & 7, s = id >> 3;
#pragma unroll 8
        for (int r = s * 32; r < s * 32 + 32; r++)
            a2 = fmaf(btg[r], wp[r * NF + ff], a2);
        red[tid] = a2;
    } else if (tid < 160) {
        int s = tid - 128;
#pragma unroll
        for (int r = s * 8; r < s * 8 + 8; r++)
            a2 = fmaf(btg[r], bpg[r], a2);
        red[tid] = a2;
    }
    __syncthreads();
    if (tid < 8) {
        float sm = 0.f;
        for (int s = 0; s < 8; s++) sm += red[s * 8 + tid];
        g_vt[g][tid] = sm;
    } else if (tid < 16) {
        int ff = tid - 8;
        float sm = 0.f;
        for (int s = 0; s < 8; s++) sm += red[64 + s * 8 + ff];
        g_vp[g][ff] = sm;
    } else if (tid == 16) {
        float sm = 0.f;
        for (int k = 0; k < 32; k++) sm += red[128 + k];
        g_c[g] = sm;
    }
}

// dual-accumulator 8-dot
#define DOT8_DUAL(res, xv, wr, init)                                     \
    do {                                                                 \
        float _a0 = fmaf((xv)[0], (wr)[0], (init));                      \
        float _a1 = (xv)[1] * (wr)[1];                                   \
        _a0 = fmaf((xv)[2], (wr)[2], _a0);                               \
        _a1 = fmaf((xv)[3], (wr)[3], _a1);                               \
        _a0 = fmaf((xv)[4], (wr)[4], _a0);                               \
        _a1 = fmaf((xv)[5], (wr)[5], _a1);                               \
        _a0 = fmaf((xv)[6], (wr)[6], _a0);                               \
        _a1 = fmaf((xv)[7], (wr)[7], _a1);                               \
        (res) = _a0 + _a1;                                               \
    } while (0)

#define LOAD8(dst, src)                                                  \
    do {                                                                 \
        float4 _v0 = ((const float4*)(src))[0];                          \
        float4 _v1 = ((const float4*)(src))[1];                          \
        (dst)[0] = _v0.x; (dst)[1] = _v0.y; (dst)[2] = _v0.z;            \
        (dst)[3] = _v0.w; (dst)[4] = _v1.x; (dst)[5] = _v1.y;            \
        (dst)[6] = _v1.z; (dst)[7] = _v1.w;                              \
    } while (0)

#define STORE8(dst, src)                                                 \
    do {                                                                 \
        ((float4*)(dst))[0] = make_float4((src)[0], (src)[1], (src)[2], (src)[3]); \
        ((float4*)(dst))[1] = make_float4((src)[4], (src)[5], (src)[6], (src)[7]); \
    } while (0)

#define FSTR 52   // batch stride (floats) for feat/states
#define SSTR 26   // batch stride for sphi
#define BPB  32   // batches per block (96 threads, 3 per batch)

// One thread per (batch, row-pair {j, j+3}): two independent softmax-row
// pipelines per thread (ILP x2); all shared-operand LDS amortized over both.
__global__ __launch_bounds__(96, 5) void gcn_rows2(
    const float* __restrict__ X,     // [B,6,8]
    const float* __restrict__ P,     // [B,6,2]
    const float* __restrict__ Wext,  // [8,8]
    const float* __restrict__ bext,  // [8]
    const float* __restrict__ Wgcn,  // [4,8,8]
    const float* __restrict__ Wact,  // [5,8]
    const float* __restrict__ bact,  // [5]
    float* __restrict__ out)         // [B,5]
{
    __shared__ __align__(16) float sWext[64];
    __shared__ __align__(16) float sM[NG][64];
    __shared__ __align__(16) float sWgcn[NG][64];
    __shared__ __align__(16) float svt[NG][NF];
    __shared__ __align__(16) float svp[NG][NF];
    __shared__ __align__(16) float sWact[40];
    __shared__ float sbext[NF], sbact[NACT], sc[NG];
    __shared__ __align__(16) float sFeat[BPB * FSTR];
    __shared__ __align__(16) float sStates[BPB * FSTR];
    __shared__ float sSphi[BPB * SSTR];

    int tid = threadIdx.x;
    if (tid < 64) sWext[tid] = Wext[tid];
    if (tid < 40) sWact[tid] = Wact[tid];
    if (tid < 32) {
        ((float*)svt)[tid] = ((const float*)g_vt)[tid];
        ((float*)svp)[tid] = ((const float*)g_vp)[tid];
    }
    if (tid < 8)  sbext[tid] = bext[tid];
    if (tid < 5)  sbact[tid] = bact[tid];
    if (tid < 4)  sc[tid]    = g_c[tid];
#pragma unroll
    for (int i = tid; i < 256; i += 96) {
        ((float*)sM)[i]    = ((const float*)g_M)[i];
        ((float*)sWgcn)[i] = Wgcn[i];
    }

    int bl = tid / 3;                  // batch-local 0..31
    int j  = tid - bl * 3;             // 0..2
    int na = j;                        // own rows: j and j+3
    int nb = j + 3;
    int b  = blockIdx.x * BPB + bl;

    // ---- distance masks for both rows (exact R1 op sequence) ----
    unsigned rowma = 0, rowmb = 0;
    {
        const float4* P4 = (const float4*)(P + b * 12);
        float4 p0 = P4[0], p1 = P4[1], p2 = P4[2];
        float px[NB] = {p0.x, p0.z, p1.x, p1.z, p2.x, p2.z};
        float py[NB] = {p0.y, p0.w, p1.y, p1.w, p2.y, p2.w};
        float rr[NB];
#pragma unroll
        for (int m = 0; m < NB; m++)
            rr[m] = __fmaf_rn(py[m], py[m], __fmul_rn(px[m], px[m]));
#pragma unroll
        for (int m = 0; m < NB; m++) {
            float dota = __fmaf_rn(py[na], py[m], __fmul_rn(px[na], px[m]));
            float d2a  = __fadd_rn(__fsub_rn(rr[na], __fmul_rn(2.0f, dota)), rr[m]);
            if (__fsqrt_rn(d2a) > 4.0f) rowma |= 1u << m;
            float dotb = __fmaf_rn(py[nb], py[m], __fmul_rn(px[nb], px[m]));
            float d2b  = __fadd_rn(__fsub_rn(rr[nb], __fmul_rn(2.0f, dotb)), rr[m]);
            if (__fsqrt_rn(d2b) > 4.0f) rowmb |= 1u << m;
        }
    }

    __syncthreads();   // weights staged

    // ---- feat for both own rows (wr loads shared) ----
    float fa[NF], fb[NF];
    {
        float xa[NF], xb[NF];
        LOAD8(xa, X + (b * NB + na) * NF);
        LOAD8(xb, X + (b * NB + nb) * NF);
#pragma unroll
        for (int f = 0; f < NF; f++) {
            float wr[NF];
            LOAD8(wr, &sWext[f * 8]);
            float ra, rb;
            DOT8_DUAL(ra, xa, wr, sbext[f]);
            DOT8_DUAL(rb, xb, wr, sbext[f]);
            fa[f] = fmaxf(ra, 0.0f);
            fb[f] = fmaxf(rb, 0.0f);
        }
    }
    STORE8(&sFeat[bl * FSTR + na * 8], fa);
    STORE8(&sFeat[bl * FSTR + nb * 8], fb);

    // ---- sphi columns for both rows (vpr loads shared) ----
#pragma unroll
    for (int g = 0; g < NG; g++) {
        float vpr[NF];
        LOAD8(vpr, svp[g]);
        float aa, ab;
        DOT8_DUAL(aa, fa, vpr, 0.0f);
        DOT8_DUAL(ab, fb, vpr, 0.0f);
        sSphi[bl * SSTR + g * 6 + na] = aa;
        sSphi[bl * SSTR + g * 6 + nb] = ab;
    }
    __syncthreads();   // feat + sphi published

    const float* Fb = &sFeat[bl * FSTR];
    const float* Sb = &sSphi[bl * SSTR];

    float gsa[NF], gsb[NF];
#pragma unroll
    for (int f = 0; f < NF; f++) { gsa[f] = 0.f; gsb[f] = 0.f; }

#pragma unroll
    for (int g = 0; g < NG; g++) {
        // tt for both rows, sharing each M-row load
        float ta[NF], tb[NF];
#pragma unroll
        for (int f = 0; f < NF; f++) { ta[f] = 0.f; tb[f] = 0.f; }
#pragma unroll
        for (int e = 0; e < NF; e++) {
            float mr[NF];
            LOAD8(mr, &sM[g][e * 8]);
            float va = fa[e], vb = fb[e];
#pragma unroll
            for (int f = 0; f < NF; f++) {
                ta[f] = fmaf(va, mr[f], ta[f]);
                tb[f] = fmaf(vb, mr[f], tb[f]);
            }
        }
        float sta, stb;
        {
            float vtr[NF];
            LOAD8(vtr, svt[g]);
            DOT8_DUAL(sta, fa, vtr, sc[g]);
            DOT8_DUAL(stb, fb, vtr, sc[g]);
        }

        // s for both rows, sharing each fm load
        float sa[NB], sb[NB];
#pragma unroll
        for (int m = 0; m < NB; m++) {
            float fm[NF];
            LOAD8(fm, &Fb[m * 8]);
            float aa, ab;
            DOT8_DUAL(aa, ta, fm, sta + Sb[g * 6 + m]);
            DOT8_DUAL(ab, tb, fm, stb + Sb[g * 6 + m]);
            sa[m] = aa * 0.0625f;     // / sqrt(256)
            sb[m] = ab * 0.0625f;
        }

        // two independent softmaxes (ILP)
        float mxa = -3.402823466e38f, mxb = -3.402823466e38f;
#pragma unroll
        for (int m = 0; m < NB; m++) {
            if (!((rowma >> m) & 1u)) mxa = fmaxf(mxa, sa[m]);
            if (!((rowmb >> m) & 1u)) mxb = fmaxf(mxb, sb[m]);
        }
        float psa = 0.f, psb = 0.f;
#pragma unroll
        for (int m = 0; m < NB; m++) {
            float ea = ((rowma >> m) & 1u) ? 0.0f : __expf(sa[m] - mxa);
            float eb = ((rowmb >> m) & 1u) ? 0.0f : __expf(sb[m] - mxb);
            sa[m] = ea; psa += ea;
            sb[m] = eb; psb += eb;
        }
        float inva = 1.0f / psa, invb = 1.0f / psb;

        // agg for both rows, sharing each fm load
        float aga[NF], agb[NF];
#pragma unroll
        for (int f = 0; f < NF; f++) { aga[f] = 0.f; agb[f] = 0.f; }
#pragma unroll
        for (int m = 0; m < NB; m++) {
            float fm[NF];
            LOAD8(fm, &Fb[m * 8]);
            float wa = sa[m] * inva, wb = sb[m] * invb;
#pragma unroll
            for (int f = 0; f < NF; f++) {
                aga[f] = fmaf(wa, fm[f], aga[f]);
                agb[f] = fmaf(wb, fm[f], agb[f]);
            }
        }

        // gcn for both rows, sharing each Wgcn-row load
#pragma unroll
        for (int o = 0; o < NF; o++) {
            float wr[NF];
            LOAD8(wr, &sWgcn[g][o * 8]);
            float aa, ab;
            DOT8_DUAL(aa, aga, wr, 0.0f);
            DOT8_DUAL(ab, agb, wr, 0.0f);
            gsa[o] += fmaxf(aa, 0.0f);
            gsb[o] += fmaxf(ab, 0.0f);
        }
    }

    // ---- state rows: residual + mean over NG ----
    {
        float xa[NF], xb[NF];
        LOAD8(xa, X + (b * NB + na) * NF);
        LOAD8(xb, X + (b * NB + nb) * NF);
        float sta[NF], stb[NF];
#pragma unroll
        for (int f = 0; f < NF; f++) {
            sta[f] = fmaf(gsa[f], 0.25f, xa[f]);
            stb[f] = fmaf(gsb[f], 0.25f, xb[f]);
        }
        STORE8(&sStates[bl * FSTR + na * 8], sta);
        STORE8(&sStates[bl * FSTR + nb * 8], stb);
    }
    __syncthreads();

    // ---- max-pool + activity head: one thread per batch ----
    if (tid < BPB) {
        const float* Stb = &sStates[tid * FSTR];
        float pl[NF];
        LOAD8(pl, &Stb[0]);
#pragma unroll
        for (int m = 1; m < NB; m++) {
            float sv[NF];
            LOAD8(sv, &Stb[m * 8]);
#pragma unroll
            for (int f = 0; f < NF; f++) pl[f] = fmaxf(pl[f], sv[f]);
        }
        float* ob = out + (blockIdx.x * BPB + tid) * NACT;
#pragma unroll
        for (int a = 0; a < NACT; a++) {
            float wr[NF];
            LOAD8(wr, &sWact[a * 8]);
            float acc;
            DOT8_DUAL(acc, pl, wr, sbact[a]);
            ob[a] = acc;
        }
    }
}

extern "C" void kernel_launch(void* const* d_in, const int* in_sizes, int n_in,
                              void* d_out, int out_size)
{
    const float* X    = (const float*)d_in[0];
    const float* P    = (const float*)d_in[1];
    const float* Wext = (const float*)d_in[2];
    const float* bext = (const float*)d_in[3];
    const float* Wt   = (const float*)d_in[4];
    const float* bt   = (const float*)d_in[5];
    const float* Wp   = (const float*)d_in[6];
    const float* bp   = (const float*)d_in[7];
    const float* Wgcn = (const float*)d_in[8];
    const float* Wact = (const float*)d_in[9];
    const float* bact = (const float*)d_in[10];

    precompute_kernel<<<NG, 256>>>(Wt, bt, Wp, bp);
    gcn_rows2<<<BTOT / BPB, 96>>>(X, P, Wext, bext, Wgcn, Wact, bact,
                                  (float*)d_out);
}

// round 15
// speedup vs baseline: 1.1604x; 1.1604x over previous
#include <cuda_runtime.h>
#include <math.h>

#define NG   4
#define NB   6
#define NF   8
#define NFRR 256
#define NACT 5
#define BTOT 32768

// Precomputed factorization of relation similarity:
// sim[g,n,m]*16 = feat_n^T M_g feat_m + vt_g.feat_n + vp_g.feat_m + c_g
__device__ float g_M[NG][NF * NF];
__device__ float g_vt[NG][NF];
__device__ float g_vp[NG][NF];
__device__ float g_c[NG];

__global__ void precompute_kernel(const float* __restrict__ Wt,
                                  const float* __restrict__ bt,
                                  const float* __restrict__ Wp,
                                  const float* __restrict__ bp)
{
    int g   = blockIdx.x;
    int tid = threadIdx.x;                 // 256 threads
    const float* wt  = Wt + g * NFRR * NF;
    const float* wp  = Wp + g * NFRR * NF;
    const float* btg = bt + g * NFRR;
    const float* bpg = bp + g * NFRR;
    __shared__ float red[256];

    int ef = tid & 63, q = tid >> 6;
    int e  = ef >> 3,  f = ef & 7;
    float acc = 0.f;
#pragma unroll 8
    for (int r = q * 64; r < q * 64 + 64; r++)
        acc = fmaf(wt[r * NF + e], wp[r * NF + f], acc);
    red[tid] = acc;
    __syncthreads();
    if (q == 0)
        g_M[g][ef] = (red[ef] + red[64 + ef]) + (red[128 + ef] + red[192 + ef]);
    __syncthreads();

    float a2 = 0.f;
    if (tid < 64) {
        int ff = tid & 7, s = tid >> 3;
#pragma unroll 8
        for (int r = s * 32; r < s * 32 + 32; r++)
            a2 = fmaf(wt[r * NF + ff], bpg[r], a2);
        red[tid] = a2;
    } else if (tid < 128) {
        int id = tid - 64, ff = id & 7, s = id >> 3;
#pragma unroll 8
        for (int r = s * 32; r < s * 32 + 32; r++)
            a2 = fmaf(btg[r], wp[r * NF + ff], a2);
        red[tid] = a2;
    } else if (tid < 160) {
        int s = tid - 128;
#pragma unroll
        for (int r = s * 8; r < s * 8 + 8; r++)
            a2 = fmaf(btg[r], bpg[r], a2);
        red[tid] = a2;
    }
    __syncthreads();
    if (tid < 8) {
        float sm = 0.f;
        for (int s = 0; s < 8; s++) sm += red[s * 8 + tid];
        g_vt[g][tid] = sm;
    } else if (tid < 16) {
        int ff = tid - 8;
        float sm = 0.f;
        for (int s = 0; s < 8; s++) sm += red[64 + s * 8 + ff];
        g_vp[g][ff] = sm;
    } else if (tid == 16) {
        float sm = 0.f;
        for (int k = 0; k < 32; k++) sm += red[128 + k];
        g_c[g] = sm;
    }
}

// dual-accumulator 8-dot
#define DOT8_DUAL(res, xv, wr, init)                                     \
    do {                                                                 \
        float _a0 = fmaf((xv)[0], (wr)[0], (init));                      \
        float _a1 = (xv)[1] * (wr)[1];                                   \
        _a0 = fmaf((xv)[2], (wr)[2], _a0);                               \
        _a1 = fmaf((xv)[3], (wr)[3], _a1);                               \
        _a0 = fmaf((xv)[4], (wr)[4], _a0);                               \
        _a1 = fmaf((xv)[5], (wr)[5], _a1);                               \
        _a0 = fmaf((xv)[6], (wr)[6], _a0);                               \
        _a1 = fmaf((xv)[7], (wr)[7], _a1);                               \
        (res) = _a0 + _a1;                                               \
    } while (0)

#define LOAD8(dst, src)                                                  \
    do {                                                                 \
        float4 _v0 = ((const float4*)(src))[0];                          \
        float4 _v1 = ((const float4*)(src))[1];                          \
        (dst)[0] = _v0.x; (dst)[1] = _v0.y; (dst)[2] = _v0.z;            \
        (dst)[3] = _v0.w; (dst)[4] = _v1.x; (dst)[5] = _v1.y;            \
        (dst)[6] = _v1.z; (dst)[7] = _v1.w;                              \
    } while (0)

#define STORE8(dst, src)                                                 \
    do {                                                                 \
        ((float4*)(dst))[0] = make_float4((src)[0], (src)[1], (src)[2], (src)[3]); \
        ((float4*)(dst))[1] = make_float4((src)[4], (src)[5], (src)[6], (src)[7]); \
    } while (0)

#define FSTR 52   // batch stride (floats) for feat/states
#define SSTR 26   // batch stride for sphi
#define BPB  16   // batches per block (96 threads, 6 per batch)

// One thread per (batch, box-row).  After the publish barrier every thread
// pulls all 6 feat rows into registers (F6) so the s/agg chains in the
// g-loop are pure register FMA (no LDS latency on the critical path).
// Mask is an additive bias (0 / -1e30), removing softmax select logic.
__global__ __launch_bounds__(96, 5) void gcn_regs(
    const float* __restrict__ X,     // [B,6,8]
    const float* __restrict__ P,     // [B,6,2]
    const float* __restrict__ Wext,  // [8,8]
    const float* __restrict__ bext,  // [8]
    const float* __restrict__ Wgcn,  // [4,8,8]
    const float* __restrict__ Wact,  // [5,8]
    const float* __restrict__ bact,  // [5]
    float* __restrict__ out)         // [B,5]
{
    __shared__ __align__(16) float sWext[64];
    __shared__ __align__(16) float sM[NG][64];
    __shared__ __align__(16) float sWgcn[NG][64];
    __shared__ __align__(16) float svt[NG][NF];
    __shared__ __align__(16) float svp[NG][NF];
    __shared__ __align__(16) float sWact[40];
    __shared__ float sbext[NF], sbact[NACT], sc[NG];
    __shared__ __align__(16) float sFeat[BPB * FSTR];
    __shared__ __align__(16) float sStates[BPB * FSTR];
    __shared__ float sSphi[BPB * SSTR];

    int tid = threadIdx.x;
    if (tid < 64) sWext[tid] = Wext[tid];
    if (tid < 40) sWact[tid] = Wact[tid];
    if (tid < 32) {
        ((float*)svt)[tid] = ((const float*)g_vt)[tid];
        ((float*)svp)[tid] = ((const float*)g_vp)[tid];
    }
    if (tid < 8)  sbext[tid] = bext[tid];
    if (tid < 5)  sbact[tid] = bact[tid];
    if (tid < 4)  sc[tid]    = g_c[tid];
#pragma unroll
    for (int i = tid; i < 256; i += 96) {
        ((float*)sM)[i]    = ((const float*)g_M)[i];
        ((float*)sWgcn)[i] = Wgcn[i];
    }

    int bl = tid / 6;                  // batch-local 0..15
    int n  = tid - bl * 6;             // own box row 0..5
    int b  = blockIdx.x * BPB + bl;

    // ---- distance mask as additive bias (exact R1 comparison sequence) ----
    float mb[NB];
    {
        const float4* P4 = (const float4*)(P + b * 12);
        float4 p0 = P4[0], p1 = P4[1], p2 = P4[2];
        float px[NB] = {p0.x, p0.z, p1.x, p1.z, p2.x, p2.z};
        float py[NB] = {p0.y, p0.w, p1.y, p1.w, p2.y, p2.w};
        float rr[NB];
#pragma unroll
        for (int m = 0; m < NB; m++)
            rr[m] = __fmaf_rn(py[m], py[m], __fmul_rn(px[m], px[m]));
#pragma unroll
        for (int m = 0; m < NB; m++) {
            float dot = __fmaf_rn(py[n], py[m], __fmul_rn(px[n], px[m]));
            float d2  = __fadd_rn(__fsub_rn(rr[n], __fmul_rn(2.0f, dot)), rr[m]);
            mb[m] = (__fsqrt_rn(d2) > 4.0f) ? -1.0e30f : 0.0f;
        }
    }

    __syncthreads();   // weights staged

    // ---- own feat row ----
    float featr[NF];
    {
        float xr[NF];
        LOAD8(xr, X + (b * NB + n) * NF);
#pragma unroll
        for (int f = 0; f < NF; f++) {
            float wr[NF];
            LOAD8(wr, &sWext[f * 8]);
            float a;
            DOT8_DUAL(a, xr, wr, sbext[f]);
            featr[f] = fmaxf(a, 0.0f);
        }
    }
    STORE8(&sFeat[bl * FSTR + n * 8], featr);

    // ---- own sphi column: sphi[g][n] = vp_g . feat_n ----
#pragma unroll
    for (int g = 0; g < NG; g++) {
        float vpr[NF];
        LOAD8(vpr, svp[g]);
        float a;
        DOT8_DUAL(a, featr, vpr, 0.0f);
        sSphi[bl * SSTR + g * 6 + n] = a;
    }
    __syncthreads();   // feat + sphi published

    // ---- pull ALL 6 feat rows into registers (only LDS of feat, ever) ----
    float F6[NB][NF];
#pragma unroll
    for (int m = 0; m < NB; m++)
        LOAD8(F6[m], &sFeat[bl * FSTR + m * 8]);

    const float* Sb = &sSphi[bl * SSTR];

    float gsum[NF];
#pragma unroll
    for (int f = 0; f < NF; f++) gsum[f] = 0.f;

#pragma unroll
    for (int g = 0; g < NG; g++) {
        // tt[f] = sum_e featr[e] * M[e][f]
        float tt[NF];
#pragma unroll
        for (int f = 0; f < NF; f++) tt[f] = 0.f;
#pragma unroll
        for (int e = 0; e < NF; e++) {
            float mr[NF];
            LOAD8(mr, &sM[g][e * 8]);
            float fv = featr[e];
#pragma unroll
            for (int f = 0; f < NF; f++) tt[f] = fmaf(fv, mr[f], tt[f]);
        }
        float st;
        {
            float vtr[NF];
            LOAD8(vtr, svt[g]);
            DOT8_DUAL(st, featr, vtr, sc[g]);
        }

        // s[m]: pure register dot + scale with mask folded in as FFMA
        float s[NB];
#pragma unroll
        for (int m = 0; m < NB; m++) {
            float a;
            DOT8_DUAL(a, tt, F6[m], st + Sb[g * 6 + m]);
            s[m] = fmaf(a, 0.0625f, mb[m]);   // /sqrt(256) + mask bias
        }

        // unconditional softmax (masked entries ~ -1e30 -> exp underflows to 0)
        float mx = -3.402823466e38f;
#pragma unroll
        for (int m = 0; m < NB; m++) mx = fmaxf(mx, s[m]);
        float ps = 0.f;
#pragma unroll
        for (int m = 0; m < NB; m++) {
            float e_ = __expf(s[m] - mx);
            s[m] = e_;
            ps += e_;
        }
        float inv = 1.0f / ps;

        // agg: pure register FMA
        float agg[NF];
#pragma unroll
        for (int f = 0; f < NF; f++) agg[f] = 0.f;
#pragma unroll
        for (int m = 0; m < NB; m++) {
            float wv = s[m] * inv;
#pragma unroll
            for (int f = 0; f < NF; f++)
                agg[f] = fmaf(wv, F6[m][f], agg[f]);
        }

#pragma unroll
        for (int o = 0; o < NF; o++) {
            float wr[NF];
            LOAD8(wr, &sWgcn[g][o * 8]);
            float a;
            DOT8_DUAL(a, agg, wr, 0.0f);
            gsum[o] += fmaxf(a, 0.0f);
        }
    }

    // ---- own state row: residual + mean over NG ----
    {
        float xr[NF];
        LOAD8(xr, X + (b * NB + n) * NF);
        float stt[NF];
#pragma unroll
        for (int f = 0; f < NF; f++)
            stt[f] = fmaf(gsum[f], 0.25f, xr[f]);
        STORE8(&sStates[bl * FSTR + n * 8], stt);
    }
    __syncthreads();

    // ---- max-pool + activity head: one thread per batch ----
    if (tid < BPB) {
        const float* Stb = &sStates[tid * FSTR];
        float pl[NF];
        LOAD8(pl, &Stb[0]);
#pragma unroll
        for (int m = 1; m < NB; m++) {
            float sv[NF];
            LOAD8(sv, &Stb[m * 8]);
#pragma unroll
            for (int f = 0; f < NF; f++) pl[f] = fmaxf(pl[f], sv[f]);
        }
        float* ob = out + (blockIdx.x * BPB + tid) * NACT;
#pragma unroll
        for (int a = 0; a < NACT; a++) {
            float wr[NF];
            LOAD8(wr, &sWact[a * 8]);
            float acc;
            DOT8_DUAL(acc, pl, wr, sbact[a]);
            ob[a] = acc;
        }
    }
}

extern "C" void kernel_launch(void* const* d_in, const int* in_sizes, int n_in,
                              void* d_out, int out_size)
{
    const float* X    = (const float*)d_in[0];
    const float* P    = (const float*)d_in[1];
    const float* Wext = (const float*)d_in[2];
    const float* bext = (const float*)d_in[3];
    const float* Wt   = (const float*)d_in[4];
    const float* bt   = (const float*)d_in[5];
    const float* Wp   = (const float*)d_in[6];
    const float* bp   = (const float*)d_in[7];
    const float* Wgcn = (const float*)d_in[8];
    const float* Wact = (const float*)d_in[9];
    const float* bact = (const float*)d_in[10];

    precompute_kernel<<<NG, 256>>>(Wt, bt, Wp, bp);
    gcn_regs<<<BTOT / BPB, 96>>>(X, P, Wext, bext, Wgcn, Wact, bact,
                                 (float*)d_out);
}